// round 9
// baseline (speedup 1.0000x reference)
#include <cuda_runtime.h>
#include <math.h>

#define NB   64
#define NHP  64
#define NH_  64
#define NW_  64
#define ND   32
#define NDFF 64
#define PIX  (NH_*NW_)
#define NP   (NB*NHP)
#define FULL 0xffffffffu

// scratch
__device__ float g_feat[NP * ND];                        // [token][32]
__device__ float g_qkv [NP * 96];                        // [token][96] q|k|v
__device__ float g_attn[NP * ND];                        // [token][32]
__device__ __align__(16) float g_heads[NP * 256];        // [p]: [0,64)=rowg [64,128)=drv [128,192)=colv [192,256)=dcv

// ---------------------------------------------------------------------------
// Kernel 1: per-(b,hp) stats over 4096 elements + in_proj -> g_feat
// ---------------------------------------------------------------------------
__global__ __launch_bounds__(256) void stats_kernel(
    const float* __restrict__ a, const float* __restrict__ b,
    const float* __restrict__ layer_emb,
    const float* __restrict__ in_proj_w,   // [D,12]
    const float* __restrict__ in_proj_b)   // [D]
{
    const int p   = blockIdx.x;
    const int tid = threadIdx.x;
    const float4* a4 = (const float4*)(a + (size_t)p * PIX);
    const float4* b4 = (const float4*)(b + (size_t)p * PIX);

    float4 av0 = __ldg(&a4[tid]),       av1 = __ldg(&a4[tid + 256]);
    float4 av2 = __ldg(&a4[tid + 512]), av3 = __ldg(&a4[tid + 768]);
    float4 bv0 = __ldg(&b4[tid]),       bv1 = __ldg(&b4[tid + 256]);
    float4 bv2 = __ldg(&b4[tid + 512]), bv3 = __ldg(&b4[tid + 768]);

    float sa = 0.f, sa2 = 0.f, sb = 0.f, sb2 = 0.f, dt = 0.f;
    float mna =  3.4e38f, mxa = -3.4e38f;
    float mnb =  3.4e38f, mxb = -3.4e38f;
#define ACC(u, v)                                                   \
    { float _u = (u), _v = (v);                                      \
      sa += _u; sa2 += _u * _u; sb += _v; sb2 += _v * _v;            \
      dt += _u * _v;                                                 \
      mna = fminf(mna, _u); mxa = fmaxf(mxa, _u);                    \
      mnb = fminf(mnb, _v); mxb = fmaxf(mxb, _v); }
    ACC(av0.x, bv0.x); ACC(av0.y, bv0.y); ACC(av0.z, bv0.z); ACC(av0.w, bv0.w);
    ACC(av1.x, bv1.x); ACC(av1.y, bv1.y); ACC(av1.z, bv1.z); ACC(av1.w, bv1.w);
    ACC(av2.x, bv2.x); ACC(av2.y, bv2.y); ACC(av2.z, bv2.z); ACC(av2.w, bv2.w);
    ACC(av3.x, bv3.x); ACC(av3.y, bv3.y); ACC(av3.z, bv3.z); ACC(av3.w, bv3.w);
#undef ACC

#pragma unroll
    for (int o = 16; o; o >>= 1) {
        sa  += __shfl_down_sync(FULL, sa,  o);
        sa2 += __shfl_down_sync(FULL, sa2, o);
        sb  += __shfl_down_sync(FULL, sb,  o);
        sb2 += __shfl_down_sync(FULL, sb2, o);
        dt  += __shfl_down_sync(FULL, dt,  o);
        mna = fminf(mna, __shfl_down_sync(FULL, mna, o));
        mxa = fmaxf(mxa, __shfl_down_sync(FULL, mxa, o));
        mnb = fminf(mnb, __shfl_down_sync(FULL, mnb, o));
        mxb = fmaxf(mxb, __shfl_down_sync(FULL, mxb, o));
    }

    __shared__ float red[8][9];
    __shared__ float stats[12];
    const int w = tid >> 5, l = tid & 31;
    if (l == 0) {
        red[w][0] = sa;  red[w][1] = sa2; red[w][2] = sb;  red[w][3] = sb2;
        red[w][4] = dt;  red[w][5] = mna; red[w][6] = mxa; red[w][7] = mnb;
        red[w][8] = mxb;
    }
    __syncthreads();

    if (tid == 0) {
        float SA = red[0][0], SA2 = red[0][1], SB = red[0][2], SB2 = red[0][3];
        float DT = red[0][4], MNA = red[0][5], MXA = red[0][6];
        float MNB = red[0][7], MXB = red[0][8];
#pragma unroll
        for (int i = 1; i < 8; i++) {
            SA += red[i][0]; SA2 += red[i][1]; SB += red[i][2]; SB2 += red[i][3];
            DT += red[i][4];
            MNA = fminf(MNA, red[i][5]); MXA = fmaxf(MXA, red[i][6]);
            MNB = fminf(MNB, red[i][7]); MXB = fmaxf(MXB, red[i][8]);
        }
        const float n = (float)PIX;
        const float invn = 1.f / n, invn1 = 1.f / (n - 1.f);
        float mean_a = SA * invn;
        float std_a  = sqrtf(fmaxf((SA2 - SA * SA * invn) * invn1, 0.f));
        float mean_b = SB * invn;
        float std_b  = sqrtf(fmaxf((SB2 - SB * SB * invn) * invn1, 0.f));
        float na = sqrtf(SA2), nb = sqrtf(SB2);
        float cosv = DT / (fmaxf(na, 1e-8f) * fmaxf(nb, 1e-8f));
        float SD  = SA - SB;
        float SD2 = SA2 + SB2 - 2.f * DT;
        float mean_d = SD * invn;
        float std_d  = sqrtf(fmaxf((SD2 - SD * SD * invn) * invn1, 0.f));
        float norm_d = sqrtf(fmaxf(SD2, 0.f));
        stats[0] = mean_a; stats[1] = std_a; stats[2] = MNA;  stats[3] = MXA;
        stats[4] = mean_b; stats[5] = std_b; stats[6] = MNB;  stats[7] = MXB;
        stats[8] = mean_d; stats[9] = std_d; stats[10] = norm_d; stats[11] = cosv;
    }
    __syncthreads();

    if (tid < ND) {
        float s = __ldg(&in_proj_b[tid]) + __ldg(&layer_emb[tid]);
#pragma unroll
        for (int j = 0; j < 12; j++)
            s += stats[j] * __ldg(&in_proj_w[tid * 12 + j]);
        g_feat[(size_t)p * ND + tid] = s;
    }
}

// ---------------------------------------------------------------------------
// X1: LN1 + QKV — warp per token, smem activation broadcast (no shfl matvec)
// ---------------------------------------------------------------------------
__global__ __launch_bounds__(256) void ln1_qkv_kernel(
    const float* __restrict__ ln1_g, const float* __restrict__ ln1_b,
    const float* __restrict__ qkv_w, const float* __restrict__ qkv_b)
{
    __shared__ float wq[32 * 97];   // transposed [k][j]
    __shared__ float sqb[96];
    __shared__ __align__(16) float sx[8 * 32];

    const int tid  = threadIdx.x;
    const int lane = tid & 31;
    const int wtok = tid >> 5;
    const int token = blockIdx.x * 8 + wtok;

    for (int i = tid; i < 96 * 32; i += 256) {
        int j = i >> 5, k = i & 31;
        wq[k * 97 + j] = __ldg(&qkv_w[i]);
    }
    if (tid < 96) sqb[tid] = __ldg(&qkv_b[tid]);

    // LN1 (warp butterflies — cheap)
    float f = g_feat[token * ND + lane];
    float m = f;
#pragma unroll
    for (int o = 16; o; o >>= 1) m += __shfl_xor_sync(FULL, m, o);
    m *= (1.f / ND);
    float d = f - m;
    float v = d * d;
#pragma unroll
    for (int o = 16; o; o >>= 1) v += __shfl_xor_sync(FULL, v, o);
    float r = rsqrtf(v * (1.f / ND) + 1e-5f);
    sx[wtok * 32 + lane] = d * r * __ldg(&ln1_g[lane]) + __ldg(&ln1_b[lane]);
    __syncthreads();

    // QKV: 3 outputs per thread; activations via broadcast float4 LDS
    float s0 = sqb[lane], s1 = sqb[lane + 32], s2 = sqb[lane + 64];
    const float4* xv = (const float4*)(sx + wtok * 32);
#pragma unroll
    for (int k4 = 0; k4 < 8; k4++) {
        float4 xa = xv[k4];
        int k = k4 * 4;
        s0 = fmaf(xa.x, wq[(k+0)*97+lane],      s0);
        s0 = fmaf(xa.y, wq[(k+1)*97+lane],      s0);
        s0 = fmaf(xa.z, wq[(k+2)*97+lane],      s0);
        s0 = fmaf(xa.w, wq[(k+3)*97+lane],      s0);
        s1 = fmaf(xa.x, wq[(k+0)*97+lane+32],   s1);
        s1 = fmaf(xa.y, wq[(k+1)*97+lane+32],   s1);
        s1 = fmaf(xa.z, wq[(k+2)*97+lane+32],   s1);
        s1 = fmaf(xa.w, wq[(k+3)*97+lane+32],   s1);
        s2 = fmaf(xa.x, wq[(k+0)*97+lane+64],   s2);
        s2 = fmaf(xa.y, wq[(k+1)*97+lane+64],   s2);
        s2 = fmaf(xa.z, wq[(k+2)*97+lane+64],   s2);
        s2 = fmaf(xa.w, wq[(k+3)*97+lane+64],   s2);
    }
    g_qkv[token * 96 + lane]      = s0;
    g_qkv[token * 96 + 32 + lane] = s1;
    g_qkv[token * 96 + 64 + lane] = s2;
}

// ---------------------------------------------------------------------------
// X2: attention — block per (batch, head), thread per query
// ---------------------------------------------------------------------------
__device__ __forceinline__ float dot4(float4 a, float4 b) {
    return fmaf(a.x, b.x, fmaf(a.y, b.y, fmaf(a.z, b.z, a.w * b.w)));
}

__global__ __launch_bounds__(64) void attn_kernel()
{
    __shared__ float4 sk[64 * 4];
    __shared__ float4 sv[64 * 4];
    const int bb = blockIdx.x >> 1;
    const int h  = blockIdx.x & 1;
    const int qt = threadIdx.x;

#pragma unroll
    for (int it = 0; it < 4; it++) {
        int idx = qt + it * 64;
        int tt = idx >> 2, quad = idx & 3;
        const float* base = g_qkv + (bb * 64 + tt) * 96 + h * 16 + quad * 4;
        sk[idx] = *(const float4*)(base + 32);
        sv[idx] = *(const float4*)(base + 64);
    }
    __syncthreads();

    const float* qb = g_qkv + (bb * 64 + qt) * 96 + h * 16;
    float4 q0 = *(const float4*)(qb),     q1 = *(const float4*)(qb + 4);
    float4 q2 = *(const float4*)(qb + 8), q3 = *(const float4*)(qb + 12);

    float mx = -3.4e38f;
    for (int kk = 0; kk < 64; kk++) {
        const float4* kb = sk + kk * 4;
        float s = dot4(q0, kb[0]) + dot4(q1, kb[1]) + dot4(q2, kb[2]) + dot4(q3, kb[3]);
        mx = fmaxf(mx, s * 0.25f);
    }
    float den = 0.f;
    float4 ac0 = {0,0,0,0}, ac1 = {0,0,0,0}, ac2 = {0,0,0,0}, ac3 = {0,0,0,0};
    for (int kk = 0; kk < 64; kk++) {
        const float4* kb = sk + kk * 4;
        float s = dot4(q0, kb[0]) + dot4(q1, kb[1]) + dot4(q2, kb[2]) + dot4(q3, kb[3]);
        float e = __expf(s * 0.25f - mx);
        den += e;
        const float4* vb = sv + kk * 4;
        float4 v0 = vb[0], v1 = vb[1], v2 = vb[2], v3 = vb[3];
        ac0.x = fmaf(e, v0.x, ac0.x); ac0.y = fmaf(e, v0.y, ac0.y);
        ac0.z = fmaf(e, v0.z, ac0.z); ac0.w = fmaf(e, v0.w, ac0.w);
        ac1.x = fmaf(e, v1.x, ac1.x); ac1.y = fmaf(e, v1.y, ac1.y);
        ac1.z = fmaf(e, v1.z, ac1.z); ac1.w = fmaf(e, v1.w, ac1.w);
        ac2.x = fmaf(e, v2.x, ac2.x); ac2.y = fmaf(e, v2.y, ac2.y);
        ac2.z = fmaf(e, v2.z, ac2.z); ac2.w = fmaf(e, v2.w, ac2.w);
        ac3.x = fmaf(e, v3.x, ac3.x); ac3.y = fmaf(e, v3.y, ac3.y);
        ac3.z = fmaf(e, v3.z, ac3.z); ac3.w = fmaf(e, v3.w, ac3.w);
    }
    float inv = __fdividef(1.f, den);
    float* dst = g_attn + (bb * 64 + qt) * ND + h * 16;
    float4 o0 = {ac0.x*inv, ac0.y*inv, ac0.z*inv, ac0.w*inv};
    float4 o1 = {ac1.x*inv, ac1.y*inv, ac1.z*inv, ac1.w*inv};
    float4 o2 = {ac2.x*inv, ac2.y*inv, ac2.z*inv, ac2.w*inv};
    float4 o3 = {ac3.x*inv, ac3.y*inv, ac3.z*inv, ac3.w*inv};
    *(float4*)(dst)      = o0;
    *(float4*)(dst + 4)  = o1;
    *(float4*)(dst + 8)  = o2;
    *(float4*)(dst + 12) = o3;
}

// ---------------------------------------------------------------------------
// X3: outproj + LN2 + FFN (smem broadcast matvecs) + heads, fused
// ---------------------------------------------------------------------------
__global__ __launch_bounds__(256) void post_heads_kernel(
    const float* __restrict__ out_w, const float* __restrict__ out_b,
    const float* __restrict__ ln2_g, const float* __restrict__ ln2_b,
    const float* __restrict__ w1,    const float* __restrict__ b1,
    const float* __restrict__ w2,    const float* __restrict__ b2,
    const float* __restrict__ gate_w, const float* __restrict__ gate_b,
    const float* __restrict__ row_w,  const float* __restrict__ row_b,
    const float* __restrict__ col_w,  const float* __restrict__ col_b,
    const float* __restrict__ drow_w, const float* __restrict__ drow_b,
    const float* __restrict__ dcol_w, const float* __restrict__ dcol_b,
    const float* __restrict__ delta_scale)
{
    __shared__ float woT[32 * 33];
    __shared__ float w1T[32 * 65];
    __shared__ float w2T[64 * 33];
    __shared__ float sob[32], sb1[64], sb2[32], sgw[32];
    __shared__ __align__(16) float sao[8 * 32];
    __shared__ __align__(16) float sx[8 * 32];
    __shared__ __align__(16) float sh[8 * 64];
    __shared__ __align__(16) float sfeat[8 * 32];

    const int tid  = threadIdx.x;
    const int lane = tid & 31;
    const int wtok = tid >> 5;
    const int token = blockIdx.x * 8 + wtok;

    for (int i = tid; i < 32 * 32; i += 256) {
        int j = i >> 5, k = i & 31;
        woT[k * 33 + j] = __ldg(&out_w[i]);
    }
    for (int i = tid; i < 64 * 32; i += 256) {
        int j = i >> 5, k = i & 31;
        w1T[k * 65 + j] = __ldg(&w1[i]);
    }
    for (int i = tid; i < 32 * 64; i += 256) {
        int d = i >> 6, k = i & 63;
        w2T[k * 33 + d] = __ldg(&w2[i]);
    }
    if (tid < 32) {
        sob[tid] = __ldg(&out_b[tid]);
        sb2[tid] = __ldg(&b2[tid]);
        sgw[tid] = __ldg(&gate_w[tid]);
    }
    if (tid < 64) sb1[tid] = __ldg(&b1[tid]);

    float f = g_feat[token * ND + lane];
    sao[wtok * 32 + lane] = g_attn[token * ND + lane];
    __syncthreads();

    // out proj + residual (broadcast float4 LDS)
    {
        float s = sob[lane];
        const float4* av = (const float4*)(sao + wtok * 32);
#pragma unroll
        for (int k4 = 0; k4 < 8; k4++) {
            float4 xa = av[k4];
            int k = k4 * 4;
            s = fmaf(xa.x, woT[(k+0)*33+lane], s);
            s = fmaf(xa.y, woT[(k+1)*33+lane], s);
            s = fmaf(xa.z, woT[(k+2)*33+lane], s);
            s = fmaf(xa.w, woT[(k+3)*33+lane], s);
        }
        f += s;
    }

    // LN2 (warp butterflies)
    {
        float m = f;
#pragma unroll
        for (int o = 16; o; o >>= 1) m += __shfl_xor_sync(FULL, m, o);
        m *= (1.f / ND);
        float d = f - m;
        float v = d * d;
#pragma unroll
        for (int o = 16; o; o >>= 1) v += __shfl_xor_sync(FULL, v, o);
        float r = rsqrtf(v * (1.f / ND) + 1e-5f);
        sx[wtok * 32 + lane] = d * r * __ldg(&ln2_g[lane]) + __ldg(&ln2_b[lane]);
    }
    __syncwarp();

    // FFN1 + exact GELU: 2 outputs per thread
    {
        float y0 = sb1[lane], y1 = sb1[lane + 32];
        const float4* xv = (const float4*)(sx + wtok * 32);
#pragma unroll
        for (int k4 = 0; k4 < 8; k4++) {
            float4 xa = xv[k4];
            int k = k4 * 4;
            y0 = fmaf(xa.x, w1T[(k+0)*65+lane],    y0);
            y0 = fmaf(xa.y, w1T[(k+1)*65+lane],    y0);
            y0 = fmaf(xa.z, w1T[(k+2)*65+lane],    y0);
            y0 = fmaf(xa.w, w1T[(k+3)*65+lane],    y0);
            y1 = fmaf(xa.x, w1T[(k+0)*65+lane+32], y1);
            y1 = fmaf(xa.y, w1T[(k+1)*65+lane+32], y1);
            y1 = fmaf(xa.z, w1T[(k+2)*65+lane+32], y1);
            y1 = fmaf(xa.w, w1T[(k+3)*65+lane+32], y1);
        }
        sh[wtok * 64 + lane]      = 0.5f * y0 * (1.f + erff(y0 * 0.70710678118654752f));
        sh[wtok * 64 + 32 + lane] = 0.5f * y1 * (1.f + erff(y1 * 0.70710678118654752f));
    }
    __syncwarp();

    // FFN2 + residual
    {
        float s = sb2[lane];
        const float4* hv = (const float4*)(sh + wtok * 64);
#pragma unroll
        for (int k4 = 0; k4 < 16; k4++) {
            float4 xa = hv[k4];
            int k = k4 * 4;
            s = fmaf(xa.x, w2T[(k+0)*33+lane], s);
            s = fmaf(xa.y, w2T[(k+1)*33+lane], s);
            s = fmaf(xa.z, w2T[(k+2)*33+lane], s);
            s = fmaf(xa.w, w2T[(k+3)*33+lane], s);
        }
        f += s;
        sfeat[wtok * 32 + lane] = f;
    }
    __syncthreads();

    // heads: thread = (grp, j); weights in registers, feat broadcast from smem
    {
        const int grp = tid >> 6, j = tid & 63;
        const float* W = (grp == 0) ? row_w : (grp == 1) ? col_w
                       : (grp == 2) ? drow_w : dcol_w;
        const float* Bv = (grp == 0) ? row_b : (grp == 1) ? col_b
                        : (grp == 2) ? drow_b : dcol_b;
        float4 wreg[8];
        const float4* wv = (const float4*)(W + j * 32);
#pragma unroll
        for (int i = 0; i < 8; i++) wreg[i] = __ldg(&wv[i]);
        const float bias = __ldg(&Bv[j]);
        const float gb = __ldg(&gate_b[0]);
        const float ds = __ldg(&delta_scale[0]);
        const int p0 = blockIdx.x * 8;

#pragma unroll
        for (int i = 0; i < 8; i++) {
            const float4* fv = (const float4*)(sfeat + i * 32);
            float s = bias, g = gb;
#pragma unroll
            for (int k4 = 0; k4 < 8; k4++) {
                float4 fa = fv[k4];
                s = fmaf(fa.x, wreg[k4].x, s);
                s = fmaf(fa.y, wreg[k4].y, s);
                s = fmaf(fa.z, wreg[k4].z, s);
                s = fmaf(fa.w, wreg[k4].w, s);
                if (grp == 0) {
                    int k = k4 * 4;
                    g = fmaf(fa.x, sgw[k+0], g);
                    g = fmaf(fa.y, sgw[k+1], g);
                    g = fmaf(fa.z, sgw[k+2], g);
                    g = fmaf(fa.w, sgw[k+3], g);
                }
            }
            int off; float val;
            if (grp == 0)      { off = j;        val = s + g;  }
            else if (grp == 1) { off = 128 + j;  val = s;      }
            else if (grp == 2) { off = 64 + j;   val = s * ds; }
            else               { off = 192 + j;  val = s;      }
            g_heads[(p0 + i) * 256 + off] = val;
        }
    }
}

// ---------------------------------------------------------------------------
// merge — pure stream, reversed order for L2 reuse
// ---------------------------------------------------------------------------
__global__ __launch_bounds__(256) void merge_kernel(
    const float* __restrict__ a, const float* __restrict__ b,
    float* __restrict__ out)
{
    const int chunk = gridDim.x - 1 - blockIdx.x;
    const int gid = chunk * 256 + threadIdx.x;
    const int p  = gid >> 10;
    const int r  = gid & 1023;
    const int h  = r >> 4;
    const int w0 = r & 15;

    const float* hp = g_heads + p * 256;
    const float rg = __ldg(hp + h);
    const float dr = __ldg(hp + 64 + h);
    const float4 cv = __ldg((const float4*)(hp + 128) + w0);
    const float4 dc = __ldg((const float4*)(hp + 192) + w0);

    const float4 av = __ldcs((const float4*)a + gid);
    const float4 bv = __ldcs((const float4*)b + gid);

    float4 ov;
#define MERGE1(comp, cvc, dcc)                                          \
    { float lgt = rg + cvc;                                              \
      float m = __fdividef(1.f, 1.f + __expf(-lgt));                     \
      ov.comp = fmaf(m, av.comp - bv.comp, fmaf(dr, dcc, bv.comp)); }
    MERGE1(x, cv.x, dc.x); MERGE1(y, cv.y, dc.y);
    MERGE1(z, cv.z, dc.z); MERGE1(w, cv.w, dc.w);
#undef MERGE1
    __stcs((float4*)out + gid, ov);
}

// ---------------------------------------------------------------------------
extern "C" void kernel_launch(void* const* d_in, const int* in_sizes, int n_in,
                              void* d_out, int out_size)
{
    const float* a          = (const float*)d_in[0];
    const float* b          = (const float*)d_in[1];
    const float* layer_emb  = (const float*)d_in[2];
    const float* in_proj_w  = (const float*)d_in[3];
    const float* in_proj_b  = (const float*)d_in[4];
    const float* ln1_g      = (const float*)d_in[5];
    const float* ln1_b      = (const float*)d_in[6];
    const float* qkv_w      = (const float*)d_in[7];
    const float* qkv_b      = (const float*)d_in[8];
    const float* out_w      = (const float*)d_in[9];
    const float* out_b      = (const float*)d_in[10];
    const float* ln2_g      = (const float*)d_in[11];
    const float* ln2_b      = (const float*)d_in[12];
    const float* ffn_w1     = (const float*)d_in[13];
    const float* ffn_b1     = (const float*)d_in[14];
    const float* ffn_w2     = (const float*)d_in[15];
    const float* ffn_b2     = (const float*)d_in[16];
    const float* gate_w     = (const float*)d_in[17];
    const float* gate_b     = (const float*)d_in[18];
    const float* row_w      = (const float*)d_in[19];
    const float* row_b      = (const float*)d_in[20];
    const float* col_w      = (const float*)d_in[21];
    const float* col_b      = (const float*)d_in[22];
    const float* drow_w     = (const float*)d_in[23];
    const float* drow_b     = (const float*)d_in[24];
    const float* dcol_w     = (const float*)d_in[25];
    const float* dcol_b     = (const float*)d_in[26];
    const float* dscale     = (const float*)d_in[27];
    float* out              = (float*)d_out;

    stats_kernel<<<NP, 256>>>(a, b, layer_emb, in_proj_w, in_proj_b);
    ln1_qkv_kernel<<<NP / 8, 256>>>(ln1_g, ln1_b, qkv_w, qkv_b);
    attn_kernel<<<NB * 2, 64>>>();
    post_heads_kernel<<<NP / 8, 256>>>(out_w, out_b, ln2_g, ln2_b,
                                       ffn_w1, ffn_b1, ffn_w2, ffn_b2,
                                       gate_w, gate_b, row_w, row_b,
                                       col_w, col_b, drow_w, drow_b,
                                       dcol_w, dcol_b, dscale);
    merge_kernel<<<NP * PIX / 4 / 256, 256>>>(a, b, out);
}